// round 1
// baseline (speedup 1.0000x reference)
#include <cuda_runtime.h>
#include <cuda_bf16.h>
#include <math.h>

// ---------------- problem constants ----------------
#define Bsz 4
#define Lsz 2048
#define Hsz 2048
#define Dsz 4096
#define Nst 16
#define Rsz 128
#define Kcv 4
#define Msz (Bsz * Lsz)          // 8192
#define DBLW (Rsz + 2 * Nst)     // 160

// ---------------- scratch (device globals; no allocation) ----------------
__device__ float g_xn [(size_t)Msz * Hsz];        //  67 MB normalized x
__device__ float g_xz [(size_t)Msz * 2 * Dsz];    // 268 MB in_proj output (xs | z)
__device__ float g_xc [(size_t)Msz * Dsz];        // 134 MB conv+silu output
__device__ float g_dbl[(size_t)Msz * DBLW];       //   5 MB x_proj output
__device__ float g_dt [(size_t)Msz * Dsz];        // 134 MB softplus(dt)
__device__ float g_y  [(size_t)Msz * Dsz];        // 134 MB scan output (gated)

// ---------------- 1) x = h + r ; residual_out = x ; xn = rmsnorm(x) ----------------
__global__ __launch_bounds__(256) void add_rmsnorm_kernel(
    const float* __restrict__ h, const float* __restrict__ r,
    const float* __restrict__ w, float* __restrict__ resid_out,
    float* __restrict__ xn)
{
    int row = blockIdx.x;                 // 0..8191
    const float4* hp = (const float4*)(h + (size_t)row * Hsz);
    const float4* rp = (const float4*)(r + (size_t)row * Hsz);
    float4*       ro = (float4*)(resid_out + (size_t)row * Hsz);
    float4*       xo = (float4*)(xn + (size_t)row * Hsz);
    const float4* wp = (const float4*)w;

    int t = threadIdx.x;
    float4 v0, v1;
    {
        float4 a = hp[t],      b = rp[t];
        v0 = make_float4(a.x + b.x, a.y + b.y, a.z + b.z, a.w + b.w);
        a = hp[t + 256]; b = rp[t + 256];
        v1 = make_float4(a.x + b.x, a.y + b.y, a.z + b.z, a.w + b.w);
    }
    float s = v0.x*v0.x + v0.y*v0.y + v0.z*v0.z + v0.w*v0.w
            + v1.x*v1.x + v1.y*v1.y + v1.z*v1.z + v1.w*v1.w;

    // block reduce
    __shared__ float red[8];
    #pragma unroll
    for (int o = 16; o > 0; o >>= 1) s += __shfl_xor_sync(0xffffffffu, s, o);
    if ((t & 31) == 0) red[t >> 5] = s;
    __syncthreads();
    if (t == 0) {
        float tot = 0.f;
        #pragma unroll
        for (int i = 0; i < 8; i++) tot += red[i];
        red[0] = tot;
    }
    __syncthreads();
    float inv = rsqrtf(red[0] * (1.0f / Hsz) + 1e-5f);

    ro[t] = v0; ro[t + 256] = v1;
    float4 w0 = wp[t], w1 = wp[t + 256];
    xo[t]       = make_float4(v0.x*inv*w0.x, v0.y*inv*w0.y, v0.z*inv*w0.z, v0.w*inv*w0.w);
    xo[t + 256] = make_float4(v1.x*inv*w1.x, v1.y*inv*w1.y, v1.z*inv*w1.z, v1.w*inv*w1.w);
}

// ---------------- generic NT GEMM: C[m,n] = sum_k A[m,k] * W[n,k] ----------------
// 128x128 block tile, BK=16, 256 threads, 8x8 microtile.
// epi: 0 = none, 1 = softplus(acc + bias[n])
__global__ __launch_bounds__(256) void gemm_nt_kernel(
    const float* __restrict__ A, const float* __restrict__ W,
    const float* __restrict__ bias, float* __restrict__ C,
    int M, int N, int K, int lda, int ldb, int ldc, int epi)
{
    __shared__ float As[16][132];
    __shared__ float Ws[16][132];

    int t  = threadIdx.x;
    int tx = t & 15, ty = t >> 4;
    int m0 = blockIdx.y * 128;
    int n0 = blockIdx.x * 128;

    float acc[8][8];
    #pragma unroll
    for (int i = 0; i < 8; i++)
        #pragma unroll
        for (int j = 0; j < 8; j++) acc[i][j] = 0.f;

    for (int k0 = 0; k0 < K; k0 += 16) {
        #pragma unroll
        for (int i = 0; i < 2; i++) {
            int lin = t + i * 256;
            int row = lin >> 2;
            int cv  = (lin & 3) << 2;
            float4 v = *(const float4*)(A + (size_t)(m0 + row) * lda + k0 + cv);
            As[cv+0][row] = v.x; As[cv+1][row] = v.y;
            As[cv+2][row] = v.z; As[cv+3][row] = v.w;
        }
        #pragma unroll
        for (int i = 0; i < 2; i++) {
            int lin = t + i * 256;
            int row = lin >> 2;
            int cv  = (lin & 3) << 2;
            float4 v = make_float4(0.f, 0.f, 0.f, 0.f);
            if (n0 + row < N)
                v = *(const float4*)(W + (size_t)(n0 + row) * ldb + k0 + cv);
            Ws[cv+0][row] = v.x; Ws[cv+1][row] = v.y;
            Ws[cv+2][row] = v.z; Ws[cv+3][row] = v.w;
        }
        __syncthreads();

        #pragma unroll
        for (int kk = 0; kk < 16; kk++) {
            float4 a0 = *(const float4*)&As[kk][ty * 8];
            float4 a1 = *(const float4*)&As[kk][ty * 8 + 4];
            float4 b0 = *(const float4*)&Ws[kk][tx * 8];
            float4 b1 = *(const float4*)&Ws[kk][tx * 8 + 4];
            float av[8] = {a0.x, a0.y, a0.z, a0.w, a1.x, a1.y, a1.z, a1.w};
            float bv[8] = {b0.x, b0.y, b0.z, b0.w, b1.x, b1.y, b1.z, b1.w};
            #pragma unroll
            for (int i = 0; i < 8; i++)
                #pragma unroll
                for (int j = 0; j < 8; j++)
                    acc[i][j] = fmaf(av[i], bv[j], acc[i][j]);
        }
        __syncthreads();
    }

    #pragma unroll
    for (int i = 0; i < 8; i++) {
        int m = m0 + ty * 8 + i;
        #pragma unroll
        for (int j = 0; j < 8; j++) {
            int n = n0 + tx * 8 + j;
            if (n < N) {
                float v = acc[i][j];
                if (epi == 1) {
                    v += bias[n];
                    v = (v > 20.f) ? v : log1pf(expf(v));   // softplus
                }
                C[(size_t)m * ldc + n] = v;
            }
        }
    }
}

// ---------------- 3) causal depthwise conv (K=4) + silu ----------------
// grid: (D/256, L/CHUNK, B). thread = one (b,d) column, CHUNK l-steps.
#define CONV_CHUNK 256
__global__ __launch_bounds__(256) void conv_silu_kernel(
    const float* __restrict__ xz, const float* __restrict__ cw,
    const float* __restrict__ cb, float* __restrict__ xc)
{
    int d  = blockIdx.x * 256 + threadIdx.x;
    int l0 = blockIdx.y * CONV_CHUNK;
    int b  = blockIdx.z;
    size_t base = (size_t)b * Lsz;

    float w0 = cw[d * Kcv + 0], w1 = cw[d * Kcv + 1];
    float w2 = cw[d * Kcv + 2], w3 = cw[d * Kcv + 3];
    float bias = cb[d];

    float xm3 = (l0 >= 3) ? xz[(base + l0 - 3) * (2 * Dsz) + d] : 0.f;
    float xm2 = (l0 >= 2) ? xz[(base + l0 - 2) * (2 * Dsz) + d] : 0.f;
    float xm1 = (l0 >= 1) ? xz[(base + l0 - 1) * (2 * Dsz) + d] : 0.f;

    #pragma unroll 4
    for (int l = l0; l < l0 + CONV_CHUNK; l++) {
        float x0 = xz[(base + l) * (2 * Dsz) + d];
        float v  = fmaf(w0, xm3, fmaf(w1, xm2, fmaf(w2, xm1, fmaf(w3, x0, bias))));
        float sg = 1.f / (1.f + __expf(-v));
        xc[(base + l) * Dsz + d] = v * sg;
        xm3 = xm2; xm2 = xm1; xm1 = x0;
    }
}

// ---------------- 5) selective scan + fused epilogue ----------------
// thread = one (b,d). h[16] state in registers. y = (scan + x*D) * silu(z)
__global__ __launch_bounds__(64) void scan_kernel(
    const float* __restrict__ dt, const float* __restrict__ xc,
    const float* __restrict__ dbl, const float* __restrict__ xz,
    const float* __restrict__ A_log, const float* __restrict__ D_param,
    float* __restrict__ y)
{
    int gid = blockIdx.x * 64 + threadIdx.x;     // 0..16383
    int b = gid >> 12;                            // / 4096
    int d = gid & (Dsz - 1);

    float A[Nst], h[Nst];
    #pragma unroll
    for (int n = 0; n < Nst; n++) {
        A[n] = -expf(A_log[d * Nst + n]);
        h[n] = 0.f;
    }
    float Dp = D_param[d];
    const float* dblb = dbl + (size_t)b * Lsz * DBLW;
    size_t rbase = (size_t)b * Lsz;

    for (int l = 0; l < Lsz; l++) {
        size_t row = rbase + l;
        float dtv = dt[row * Dsz + d];
        float xv  = xc[row * Dsz + d];
        float zv  = xz[row * (2 * Dsz) + Dsz + d];

        const float* bc = dblb + (size_t)l * DBLW;
        float4 B0 = *(const float4*)(bc + Rsz +  0);
        float4 B1 = *(const float4*)(bc + Rsz +  4);
        float4 B2 = *(const float4*)(bc + Rsz +  8);
        float4 B3 = *(const float4*)(bc + Rsz + 12);
        float4 C0 = *(const float4*)(bc + Rsz + 16);
        float4 C1 = *(const float4*)(bc + Rsz + 20);
        float4 C2 = *(const float4*)(bc + Rsz + 24);
        float4 C3 = *(const float4*)(bc + Rsz + 28);
        float Bv[Nst] = {B0.x,B0.y,B0.z,B0.w, B1.x,B1.y,B1.z,B1.w,
                         B2.x,B2.y,B2.z,B2.w, B3.x,B3.y,B3.z,B3.w};
        float Cv[Nst] = {C0.x,C0.y,C0.z,C0.w, C1.x,C1.y,C1.z,C1.w,
                         C2.x,C2.y,C2.z,C2.w, C3.x,C3.y,C3.z,C3.w};

        float dtx = dtv * xv;
        float ys = 0.f;
        #pragma unroll
        for (int n = 0; n < Nst; n++) {
            float dA = __expf(dtv * A[n]);
            h[n] = fmaf(dA, h[n], dtx * Bv[n]);
            ys   = fmaf(h[n], Cv[n], ys);
        }
        float yv = fmaf(xv, Dp, ys);
        float sg = zv / (1.f + __expf(-zv));      // silu(z)
        y[row * Dsz + d] = yv * sg;
    }
}

// ---------------- launcher ----------------
extern "C" void kernel_launch(void* const* d_in, const int* in_sizes, int n_in,
                              void* d_out, int out_size)
{
    const float* hidden    = (const float*)d_in[0];
    const float* residual  = (const float*)d_in[1];
    const float* norm_w    = (const float*)d_in[2];
    const float* in_proj_w = (const float*)d_in[3];
    const float* conv_w    = (const float*)d_in[4];
    const float* conv_b    = (const float*)d_in[5];
    const float* x_proj_w  = (const float*)d_in[6];
    const float* dt_proj_w = (const float*)d_in[7];
    const float* dt_proj_b = (const float*)d_in[8];
    const float* A_log     = (const float*)d_in[9];
    const float* D_param   = (const float*)d_in[10];
    const float* out_proj_w= (const float*)d_in[11];

    float* out       = (float*)d_out;                       // (B,L,H)
    float* resid_out = out + (size_t)Msz * Hsz;             // (B,L,H)

    float *xn, *xz, *xc, *dbl, *dtb, *yb;
    cudaGetSymbolAddress((void**)&xn,  g_xn);
    cudaGetSymbolAddress((void**)&xz,  g_xz);
    cudaGetSymbolAddress((void**)&xc,  g_xc);
    cudaGetSymbolAddress((void**)&dbl, g_dbl);
    cudaGetSymbolAddress((void**)&dtb, g_dt);
    cudaGetSymbolAddress((void**)&yb,  g_y);

    // 1) x = h + r ; residual_out ; rmsnorm
    add_rmsnorm_kernel<<<Msz, 256>>>(hidden, residual, norm_w, resid_out, xn);

    // 2) xz = xn @ in_proj_w^T   (8192 x 8192, K=2048)
    {
        dim3 grid(2 * Dsz / 128, Msz / 128);
        gemm_nt_kernel<<<grid, 256>>>(xn, in_proj_w, nullptr, xz,
                                      Msz, 2 * Dsz, Hsz, Hsz, Hsz, 2 * Dsz, 0);
    }

    // 3) depthwise causal conv + silu  (xs -> xc)
    {
        dim3 grid(Dsz / 256, Lsz / CONV_CHUNK, Bsz);
        conv_silu_kernel<<<grid, 256>>>(xz, conv_w, conv_b, xc);
    }

    // 4) dbl = xc @ x_proj_w^T   (8192 x 160, K=4096)
    {
        dim3 grid((DBLW + 127) / 128, Msz / 128);
        gemm_nt_kernel<<<grid, 256>>>(xc, x_proj_w, nullptr, dbl,
                                      Msz, DBLW, Dsz, Dsz, Dsz, DBLW, 0);
    }

    // 5) dt = softplus(dbl[:, :R] @ dt_proj_w^T + b)  (8192 x 4096, K=128)
    {
        dim3 grid(Dsz / 128, Msz / 128);
        gemm_nt_kernel<<<grid, 256>>>(dbl, dt_proj_w, dt_proj_b, dtb,
                                      Msz, Dsz, Rsz, DBLW, Rsz, Dsz, 1);
    }

    // 6) selective scan + gating epilogue
    scan_kernel<<<(Bsz * Dsz) / 64, 64>>>(dtb, xc, dbl, xz, A_log, D_param, yb);

    // 7) out = y @ out_proj_w^T  (8192 x 2048, K=4096)
    {
        dim3 grid(Hsz / 128, Msz / 128);
        gemm_nt_kernel<<<grid, 256>>>(yb, out_proj_w, nullptr, out,
                                      Msz, Hsz, Dsz, Dsz, Dsz, Hsz, 0);
    }
    (void)in_sizes; (void)n_in; (void)out_size;
}

// round 5
// speedup vs baseline: 1.9174x; 1.9174x over previous
#include <cuda_runtime.h>
#include <cuda_bf16.h>
#include <math.h>
#include <stdint.h>

// ---------------- problem constants ----------------
#define Bsz 4
#define Lsz 2048
#define Hsz 2048
#define Dsz 4096
#define Nst 16
#define Rsz 128
#define Msz (Bsz * Lsz)          // 8192
#define DBLW (Rsz + 2 * Nst)     // 160

typedef __nv_bfloat16 bf16;

// ---------------- scratch (device globals; no allocation) ----------------
__device__ bf16  g_xn_hi [(size_t)Msz * Hsz];
__device__ bf16  g_xn_lo [(size_t)Msz * Hsz];
__device__ bf16  g_wip_hi[(size_t)(2*Dsz) * Hsz];
__device__ bf16  g_wip_lo[(size_t)(2*Dsz) * Hsz];
__device__ float g_xz    [(size_t)Msz * 2 * Dsz];
__device__ bf16  g_xc_hi [(size_t)Msz * Dsz];
__device__ bf16  g_xc_lo [(size_t)Msz * Dsz];
__device__ bf16  g_xpw_hi[(size_t)DBLW * Dsz];
__device__ bf16  g_xpw_lo[(size_t)DBLW * Dsz];
__device__ float g_dbl   [(size_t)Msz * DBLW];
__device__ bf16  g_dti_hi[(size_t)Msz * Rsz];
__device__ bf16  g_dti_lo[(size_t)Msz * Rsz];
__device__ bf16  g_dtw_hi[(size_t)Dsz * Rsz];
__device__ bf16  g_dtw_lo[(size_t)Dsz * Rsz];
__device__ float g_dt    [(size_t)Msz * Dsz];
__device__ bf16  g_y_hi  [(size_t)Msz * Dsz];
__device__ bf16  g_y_lo  [(size_t)Msz * Dsz];
__device__ bf16  g_opw_hi[(size_t)Hsz * Dsz];
__device__ bf16  g_opw_lo[(size_t)Hsz * Dsz];

// ---------------- helpers ----------------
__device__ __forceinline__ uint32_t smem_to_u32(const void* p) {
    uint32_t a;
    asm("{ .reg .u64 t; cvta.to.shared.u64 t, %1; cvt.u32.u64 %0, t; }" : "=r"(a) : "l"(p));
    return a;
}
__device__ __forceinline__ void ldsm4(uint32_t& r0, uint32_t& r1, uint32_t& r2, uint32_t& r3, uint32_t a) {
    asm volatile("ldmatrix.sync.aligned.m8n8.x4.shared.b16 {%0,%1,%2,%3}, [%4];"
                 : "=r"(r0), "=r"(r1), "=r"(r2), "=r"(r3) : "r"(a));
}
__device__ __forceinline__ void mma16816(float* c, uint32_t a0, uint32_t a1, uint32_t a2, uint32_t a3,
                                         uint32_t b0, uint32_t b1) {
    asm volatile("mma.sync.aligned.m16n8k16.row.col.f32.bf16.bf16.f32 "
                 "{%0,%1,%2,%3}, {%4,%5,%6,%7}, {%8,%9}, {%0,%1,%2,%3};"
                 : "+f"(c[0]), "+f"(c[1]), "+f"(c[2]), "+f"(c[3])
                 : "r"(a0), "r"(a1), "r"(a2), "r"(a3), "r"(b0), "r"(b1));
}

// ---------------- HMMA bf16x3 GEMM: C[m,n] = sum_k A[m,k]*B[n,k] ----------------
// Block tile 128x128, BK=32, 8 warps, warp tile 64x32 (2x4 warp grid).
// Static smem, single stage, plain vectorized loads (no cp.async).
// smem rows: 32 bf16 data + 8 pad = 40 elems = 80B -> conflict-free ldmatrix.
#define BMk 128
#define BNk 128
#define BKk 32
#define ROWB 80                      // bytes per smem row
#define TILEB (128 * ROWB)           // 10240 bytes per operand tile

__global__ void __launch_bounds__(256)
gemm3_kernel(const bf16* __restrict__ Ah, const bf16* __restrict__ Al,
             const bf16* __restrict__ Bh, const bf16* __restrict__ Bl,
             const float* __restrict__ bias, float* __restrict__ C,
             int N, int K, int lda, int ldb, int ldc, int epi)
{
    __shared__ __align__(16) char smem[4 * TILEB];   // 40 KB static
    uint32_t sb = smem_to_u32(smem);
    int t = threadIdx.x, wid = t >> 5, lane = t & 31;
    int m0 = blockIdx.y * BMk, n0 = blockIdx.x * BNk;
    int wm = wid >> 2, wn = wid & 3;           // warp tile: rows wm*64, cols wn*32

    float acc[4][4][4];
    #pragma unroll
    for (int i = 0; i < 4; i++)
        #pragma unroll
        for (int j = 0; j < 4; j++)
            #pragma unroll
            for (int v = 0; v < 4; v++) acc[i][j][v] = 0.f;

    // per-lane ldmatrix byte offsets
    uint32_t a_off = (uint32_t)((wm * 64 + (lane & 15)) * ROWB + ((lane >> 4) * 8) * 2);
    uint32_t b_off = (uint32_t)((wn * 32 + ((lane >> 4) & 1) * 8 + (lane & 7)) * ROWB
                                + (((lane >> 3) & 1) * 8) * 2);

    // this thread's 8 load slots (2048 16B-chunks / 256 threads)
    const int KT = K / BKk;

    for (int it = 0; it < KT; it++) {
        int k0 = it * BKk;
        __syncthreads();                        // protect prior iteration's reads
        #pragma unroll
        for (int i = 0; i < 8; i++) {
            int cid = t + i * 256;               // 0..2047
            int tile = cid >> 9;                 // 0:Ah 1:Al 2:Bh 3:Bl
            int idx  = cid & 511;
            int row  = idx >> 2;
            int ch   = idx & 3;
            const bf16* src;
            if (tile == 0)      src = Ah + (size_t)(m0 + row) * lda + k0 + ch * 8;
            else if (tile == 1) src = Al + (size_t)(m0 + row) * lda + k0 + ch * 8;
            else {
                int n  = n0 + row;
                int cr = (n < N) ? n : 0;        // OOB rows: load row 0 (affects only unstored cols)
                src = ((tile == 2) ? Bh : Bl) + (size_t)cr * ldb + k0 + ch * 8;
            }
            *(uint4*)(smem + tile * TILEB + row * ROWB + ch * 16) = *(const uint4*)src;
        }
        __syncthreads();

        #pragma unroll
        for (int ks = 0; ks < 2; ks++) {
            uint32_t bh[8], bl[8];
            uint32_t bbase = sb + 2 * TILEB + b_off + ks * 32;
            ldsm4(bh[0], bh[1], bh[2], bh[3], bbase);
            ldsm4(bh[4], bh[5], bh[6], bh[7], bbase + 16 * ROWB);
            bbase += TILEB;
            ldsm4(bl[0], bl[1], bl[2], bl[3], bbase);
            ldsm4(bl[4], bl[5], bl[6], bl[7], bbase + 16 * ROWB);

            #pragma unroll
            for (int mi = 0; mi < 4; mi++) {
                uint32_t ah0, ah1, ah2, ah3, al0, al1, al2, al3;
                uint32_t abase = sb + a_off + mi * 16 * ROWB + ks * 32;
                ldsm4(ah0, ah1, ah2, ah3, abase);
                ldsm4(al0, al1, al2, al3, abase + TILEB);
                #pragma unroll
                for (int j = 0; j < 4; j++) {
                    mma16816(acc[mi][j], ah0, ah1, ah2, ah3, bh[j*2], bh[j*2+1]);
                    mma16816(acc[mi][j], ah0, ah1, ah2, ah3, bl[j*2], bl[j*2+1]);
                    mma16816(acc[mi][j], al0, al1, al2, al3, bh[j*2], bh[j*2+1]);
                }
            }
        }
    }

    // epilogue: direct register -> gmem stores
    #pragma unroll
    for (int mi = 0; mi < 4; mi++) {
        int row = m0 + wm * 64 + mi * 16 + (lane >> 2);
        #pragma unroll
        for (int j = 0; j < 4; j++) {
            int col = n0 + wn * 32 + j * 8 + (lane & 3) * 2;
            if (col < N) {
                float v0 = acc[mi][j][0], v1 = acc[mi][j][1];
                float v2 = acc[mi][j][2], v3 = acc[mi][j][3];
                if (epi == 1) {
                    float b0 = bias[col], b1 = bias[col + 1];
                    v0 += b0; v1 += b1; v2 += b0; v3 += b1;
                    v0 = (v0 > 0.f) ? v0 + log1pf(__expf(-v0)) : log1pf(__expf(v0));
                    v1 = (v1 > 0.f) ? v1 + log1pf(__expf(-v1)) : log1pf(__expf(v1));
                    v2 = (v2 > 0.f) ? v2 + log1pf(__expf(-v2)) : log1pf(__expf(v2));
                    v3 = (v3 > 0.f) ? v3 + log1pf(__expf(-v3)) : log1pf(__expf(v3));
                }
                *(float2*)(C + (size_t)row * ldc + col)       = make_float2(v0, v1);
                *(float2*)(C + (size_t)(row + 8) * ldc + col) = make_float2(v2, v3);
            }
        }
    }
}

// ---------------- 1) x = h + r ; residual_out = x ; xn_hi/lo = rmsnorm(x) ----------------
__global__ __launch_bounds__(256) void add_rmsnorm_kernel(
    const float* __restrict__ h, const float* __restrict__ r,
    const float* __restrict__ w, float* __restrict__ resid_out,
    bf16* __restrict__ xh, bf16* __restrict__ xl)
{
    int row = blockIdx.x;
    const float4* hp = (const float4*)(h + (size_t)row * Hsz);
    const float4* rp = (const float4*)(r + (size_t)row * Hsz);
    float4*       ro = (float4*)(resid_out + (size_t)row * Hsz);
    const float4* wp = (const float4*)w;
    int t = threadIdx.x;

    float4 v0, v1;
    { float4 a = hp[t], b = rp[t];
      v0 = make_float4(a.x+b.x, a.y+b.y, a.z+b.z, a.w+b.w);
      a = hp[t+256]; b = rp[t+256];
      v1 = make_float4(a.x+b.x, a.y+b.y, a.z+b.z, a.w+b.w); }
    float s = v0.x*v0.x+v0.y*v0.y+v0.z*v0.z+v0.w*v0.w
            + v1.x*v1.x+v1.y*v1.y+v1.z*v1.z+v1.w*v1.w;
    __shared__ float red[8];
    #pragma unroll
    for (int o = 16; o > 0; o >>= 1) s += __shfl_xor_sync(0xffffffffu, s, o);
    if ((t & 31) == 0) red[t >> 5] = s;
    __syncthreads();
    if (t == 0) { float tot = 0.f; for (int i = 0; i < 8; i++) tot += red[i]; red[0] = tot; }
    __syncthreads();
    float inv = rsqrtf(red[0] * (1.0f / Hsz) + 1e-5f);

    ro[t] = v0; ro[t + 256] = v1;
    float4 w0 = wp[t], w1 = wp[t + 256];
    float o0[8] = {v0.x*inv*w0.x, v0.y*inv*w0.y, v0.z*inv*w0.z, v0.w*inv*w0.w,
                   v1.x*inv*w1.x, v1.y*inv*w1.y, v1.z*inv*w1.z, v1.w*inv*w1.w};
    size_t base = (size_t)row * Hsz;
    #pragma unroll
    for (int j = 0; j < 4; j++) {
        bf16 hh = __float2bfloat16(o0[j]);
        xh[base + t*4 + j] = hh;
        xl[base + t*4 + j] = __float2bfloat16(o0[j] - __bfloat162float(hh));
    }
    #pragma unroll
    for (int j = 0; j < 4; j++) {
        bf16 hh = __float2bfloat16(o0[4 + j]);
        xh[base + 1024 + t*4 + j] = hh;
        xl[base + 1024 + t*4 + j] = __float2bfloat16(o0[4 + j] - __bfloat162float(hh));
    }
}

// ---------------- generic f32 -> (hi,lo) bf16 ----------------
__global__ __launch_bounds__(256) void cvt_hilo_kernel(
    const float* __restrict__ s, bf16* __restrict__ hi, bf16* __restrict__ lo, size_t n)
{
    size_t i = (size_t)blockIdx.x * 256 + threadIdx.x;
    size_t stride = (size_t)gridDim.x * 256;
    for (; i < n; i += stride) {
        float v = s[i];
        bf16 h = __float2bfloat16(v);
        hi[i] = h;
        lo[i] = __float2bfloat16(v - __bfloat162float(h));
    }
}

// dbl[:, 0:128] -> dt_in hi/lo
__global__ __launch_bounds__(256) void cvt_dtin_kernel(
    const float* __restrict__ dbl, bf16* __restrict__ hi, bf16* __restrict__ lo)
{
    int i = blockIdx.x * 256 + threadIdx.x;   // Msz*Rsz threads
    int m = i >> 7, r = i & 127;
    float v = dbl[(size_t)m * DBLW + r];
    bf16 h = __float2bfloat16(v);
    hi[i] = h;
    lo[i] = __float2bfloat16(v - __bfloat162float(h));
}

// ---------------- 3) causal depthwise conv (K=4) + silu -> hi/lo ----------------
#define CONV_CHUNK 256
__global__ __launch_bounds__(256) void conv_silu_kernel(
    const float* __restrict__ xz, const float* __restrict__ cw,
    const float* __restrict__ cb, bf16* __restrict__ xh, bf16* __restrict__ xl)
{
    int d  = blockIdx.x * 256 + threadIdx.x;
    int l0 = blockIdx.y * CONV_CHUNK;
    int b  = blockIdx.z;
    size_t base = (size_t)b * Lsz;

    float w0 = cw[d*4+0], w1 = cw[d*4+1], w2 = cw[d*4+2], w3 = cw[d*4+3];
    float bias = cb[d];
    float xm3 = (l0 >= 3) ? xz[(base + l0 - 3) * (2*Dsz) + d] : 0.f;
    float xm2 = (l0 >= 2) ? xz[(base + l0 - 2) * (2*Dsz) + d] : 0.f;
    float xm1 = (l0 >= 1) ? xz[(base + l0 - 1) * (2*Dsz) + d] : 0.f;

    #pragma unroll 4
    for (int l = l0; l < l0 + CONV_CHUNK; l++) {
        float x0 = xz[(base + l) * (2*Dsz) + d];
        float v  = fmaf(w0, xm3, fmaf(w1, xm2, fmaf(w2, xm1, fmaf(w3, x0, bias))));
        float sv = v / (1.f + __expf(-v));
        bf16 hh = __float2bfloat16(sv);
        xh[(base + l) * Dsz + d] = hh;
        xl[(base + l) * Dsz + d] = __float2bfloat16(sv - __bfloat162float(hh));
        xm3 = xm2; xm2 = xm1; xm1 = x0;
    }
}

// ---------------- 5) selective scan: 4 lanes per (b,d), split over N ----------------
__global__ __launch_bounds__(128) void scan4_kernel(
    const float* __restrict__ dt, const bf16* __restrict__ xch, const bf16* __restrict__ xcl,
    const float* __restrict__ dbl, const float* __restrict__ xz,
    const float* __restrict__ A_log, const float* __restrict__ D_param,
    bf16* __restrict__ yh, bf16* __restrict__ yl)
{
    int gid = blockIdx.x * 128 + threadIdx.x;    // 65536 threads
    int sub = gid & 3;
    int pr  = gid >> 2;                          // (b,d)
    int d = pr & (Dsz - 1);
    int b = pr >> 12;

    float A[4], h[4];
    #pragma unroll
    for (int j = 0; j < 4; j++) {
        A[j] = -expf(A_log[d * Nst + sub * 4 + j]);
        h[j] = 0.f;
    }
    float Dp = D_param[d];
    size_t rb = (size_t)b * Lsz;

    for (int l = 0; l < Lsz; l++) {
        size_t row = rb + l;
        float dtv = dt[row * Dsz + d];
        float xv  = __bfloat162float(xch[row * Dsz + d]) + __bfloat162float(xcl[row * Dsz + d]);
        float zv  = xz[row * (2*Dsz) + Dsz + d];
        const float* bc = dbl + row * DBLW;
        float4 Bv = *(const float4*)(bc + Rsz + sub * 4);
        float4 Cv = *(const float4*)(bc + Rsz + Nst + sub * 4);

        float dtx = dtv * xv;
        float ys = 0.f;
        h[0] = fmaf(__expf(dtv * A[0]), h[0], dtx * Bv.x); ys = fmaf(h[0], Cv.x, ys);
        h[1] = fmaf(__expf(dtv * A[1]), h[1], dtx * Bv.y); ys = fmaf(h[1], Cv.y, ys);
        h[2] = fmaf(__expf(dtv * A[2]), h[2], dtx * Bv.z); ys = fmaf(h[2], Cv.z, ys);
        h[3] = fmaf(__expf(dtv * A[3]), h[3], dtx * Bv.w); ys = fmaf(h[3], Cv.w, ys);
        ys += __shfl_xor_sync(0xffffffffu, ys, 1);
        ys += __shfl_xor_sync(0xffffffffu, ys, 2);

        if (sub == 0) {
            float yv = fmaf(xv, Dp, ys);
            float sg = zv / (1.f + __expf(-zv));
            float o  = yv * sg;
            bf16 hh = __float2bfloat16(o);
            yh[row * Dsz + d] = hh;
            yl[row * Dsz + d] = __float2bfloat16(o - __bfloat162float(hh));
        }
    }
}

// ---------------- launcher ----------------
extern "C" void kernel_launch(void* const* d_in, const int* in_sizes, int n_in,
                              void* d_out, int out_size)
{
    const float* hidden    = (const float*)d_in[0];
    const float* residual  = (const float*)d_in[1];
    const float* norm_w    = (const float*)d_in[2];
    const float* in_proj_w = (const float*)d_in[3];
    const float* conv_w    = (const float*)d_in[4];
    const float* conv_b    = (const float*)d_in[5];
    const float* x_proj_w  = (const float*)d_in[6];
    const float* dt_proj_w = (const float*)d_in[7];
    const float* dt_proj_b = (const float*)d_in[8];
    const float* A_log     = (const float*)d_in[9];
    const float* D_param   = (const float*)d_in[10];
    const float* out_proj_w= (const float*)d_in[11];

    float* out       = (float*)d_out;
    float* resid_out = out + (size_t)Msz * Hsz;

    bf16 *xnh,*xnl,*wih,*wil,*xch,*xcl,*xph,*xpl,*dih,*dil,*dwh,*dwl,*yhh,*yll,*owh,*owl;
    float *xz,*dbl,*dtb;
    cudaGetSymbolAddress((void**)&xnh, g_xn_hi);  cudaGetSymbolAddress((void**)&xnl, g_xn_lo);
    cudaGetSymbolAddress((void**)&wih, g_wip_hi); cudaGetSymbolAddress((void**)&wil, g_wip_lo);
    cudaGetSymbolAddress((void**)&xz,  g_xz);
    cudaGetSymbolAddress((void**)&xch, g_xc_hi);  cudaGetSymbolAddress((void**)&xcl, g_xc_lo);
    cudaGetSymbolAddress((void**)&xph, g_xpw_hi); cudaGetSymbolAddress((void**)&xpl, g_xpw_lo);
    cudaGetSymbolAddress((void**)&dbl, g_dbl);
    cudaGetSymbolAddress((void**)&dih, g_dti_hi); cudaGetSymbolAddress((void**)&dil, g_dti_lo);
    cudaGetSymbolAddress((void**)&dwh, g_dtw_hi); cudaGetSymbolAddress((void**)&dwl, g_dtw_lo);
    cudaGetSymbolAddress((void**)&dtb, g_dt);
    cudaGetSymbolAddress((void**)&yhh, g_y_hi);   cudaGetSymbolAddress((void**)&yll, g_y_lo);
    cudaGetSymbolAddress((void**)&owh, g_opw_hi); cudaGetSymbolAddress((void**)&owl, g_opw_lo);

    // 1) rmsnorm (+ residual passthrough) -> xn hi/lo
    add_rmsnorm_kernel<<<Msz, 256>>>(hidden, residual, norm_w, resid_out, xnh, xnl);

    // weight conversions
    cvt_hilo_kernel<<<2048, 256>>>(in_proj_w,  wih, wil, (size_t)(2*Dsz) * Hsz);
    cvt_hilo_kernel<<<1024, 256>>>(x_proj_w,   xph, xpl, (size_t)DBLW * Dsz);
    cvt_hilo_kernel<<<1024, 256>>>(dt_proj_w,  dwh, dwl, (size_t)Dsz * Rsz);
    cvt_hilo_kernel<<<2048, 256>>>(out_proj_w, owh, owl, (size_t)Hsz * Dsz);

    // 2) in_proj: (8192 x 8192, K=2048) -> xz fp32
    {
        dim3 grid(2*Dsz / BNk, Msz / BMk);
        gemm3_kernel<<<grid, 256>>>(xnh, xnl, wih, wil, nullptr, xz,
                                    2*Dsz, Hsz, Hsz, Hsz, 2*Dsz, 0);
    }

    // 3) conv + silu -> xc hi/lo
    {
        dim3 grid(Dsz/256, Lsz/CONV_CHUNK, Bsz);
        conv_silu_kernel<<<grid, 256>>>(xz, conv_w, conv_b, xch, xcl);
    }

    // 4) x_proj: (8192 x 160, K=4096) -> dbl fp32
    {
        dim3 grid((DBLW + BNk - 1)/BNk, Msz / BMk);
        gemm3_kernel<<<grid, 256>>>(xch, xcl, xph, xpl, nullptr, dbl,
                                    DBLW, Dsz, Dsz, Dsz, DBLW, 0);
    }

    // extract dt_in hi/lo from dbl[:, :128]
    cvt_dtin_kernel<<<(Msz * Rsz)/256, 256>>>(dbl, dih, dil);

    // 5) dt: (8192 x 4096, K=128), softplus(+bias) -> dt fp32
    {
        dim3 grid(Dsz / BNk, Msz / BMk);
        gemm3_kernel<<<grid, 256>>>(dih, dil, dwh, dwl, dt_proj_b, dtb,
                                    Dsz, Rsz, Rsz, Rsz, Dsz, 1);
    }

    // 6) selective scan + gating -> y hi/lo
    scan4_kernel<<<(Bsz * Dsz * 4)/128, 128>>>(dtb, xch, xcl, dbl, xz, A_log, D_param, yhh, yll);

    // 7) out_proj: (8192 x 2048, K=4096) -> out fp32
    {
        dim3 grid(Hsz / BNk, Msz / BMk);
        gemm3_kernel<<<grid, 256>>>(yhh, yll, owh, owl, nullptr, out,
                                    Hsz, Dsz, Dsz, Dsz, Hsz, 0);
    }
    (void)in_sizes; (void)n_in; (void)out_size;
}

// round 6
// speedup vs baseline: 1.9521x; 1.0181x over previous
#include <cuda_runtime.h>
#include <cuda_bf16.h>
#include <math.h>
#include <stdint.h>

// ---------------- problem constants ----------------
#define Bsz 4
#define Lsz 2048
#define Hsz 2048
#define Dsz 4096
#define Nst 16
#define Rsz 128
#define Msz (Bsz * Lsz)          // 8192
#define DBLW (Rsz + 2 * Nst)     // 160

typedef __nv_bfloat16 bf16;

// ---------------- scratch (device globals; no allocation) ----------------
__device__ bf16  g_xn_hi [(size_t)Msz * Hsz];
__device__ bf16  g_xn_lo [(size_t)Msz * Hsz];
__device__ bf16  g_wip_hi[(size_t)(2*Dsz) * Hsz];
__device__ bf16  g_wip_lo[(size_t)(2*Dsz) * Hsz];
__device__ float g_xz    [(size_t)Msz * 2 * Dsz];
__device__ bf16  g_xc_hi [(size_t)Msz * Dsz];
__device__ bf16  g_xc_lo [(size_t)Msz * Dsz];
__device__ bf16  g_xpw_hi[(size_t)DBLW * Dsz];
__device__ bf16  g_xpw_lo[(size_t)DBLW * Dsz];
__device__ float g_dbl   [(size_t)Msz * DBLW];
__device__ bf16  g_dti_hi[(size_t)Msz * Rsz];
__device__ bf16  g_dti_lo[(size_t)Msz * Rsz];
__device__ bf16  g_dtw_hi[(size_t)Dsz * Rsz];
__device__ bf16  g_dtw_lo[(size_t)Dsz * Rsz];
__device__ float g_dt    [(size_t)Msz * Dsz];
__device__ bf16  g_y_hi  [(size_t)Msz * Dsz];
__device__ bf16  g_y_lo  [(size_t)Msz * Dsz];
__device__ bf16  g_opw_hi[(size_t)Hsz * Dsz];
__device__ bf16  g_opw_lo[(size_t)Hsz * Dsz];

// ---------------- helpers ----------------
__device__ __forceinline__ uint32_t smem_to_u32(const void* p) {
    uint32_t a;
    asm("{ .reg .u64 t; cvta.to.shared.u64 t, %1; cvt.u32.u64 %0, t; }" : "=r"(a) : "l"(p));
    return a;
}
__device__ __forceinline__ void ldsm4(uint32_t& r0, uint32_t& r1, uint32_t& r2, uint32_t& r3, uint32_t a) {
    asm volatile("ldmatrix.sync.aligned.m8n8.x4.shared.b16 {%0,%1,%2,%3}, [%4];"
                 : "=r"(r0), "=r"(r1), "=r"(r2), "=r"(r3) : "r"(a));
}
__device__ __forceinline__ void mma16816(float* c, uint32_t a0, uint32_t a1, uint32_t a2, uint32_t a3,
                                         uint32_t b0, uint32_t b1) {
    asm volatile("mma.sync.aligned.m16n8k16.row.col.f32.bf16.bf16.f32 "
                 "{%0,%1,%2,%3}, {%4,%5,%6,%7}, {%8,%9}, {%0,%1,%2,%3};"
                 : "+f"(c[0]), "+f"(c[1]), "+f"(c[2]), "+f"(c[3])
                 : "r"(a0), "r"(a1), "r"(a2), "r"(a3), "r"(b0), "r"(b1));
}

// ---------------- HMMA bf16x3 GEMM: C[m,n] = sum_k A[m,k]*B[n,k] ----------------
// Block tile 128x128, BK=32, 8 warps, warp tile 64x32 (2x4 warp grid).
// Static smem single stage + REGISTER-PREFETCH pipeline (plain LDG/STS, no cp.async).
// smem rows: 32 bf16 data + 8 pad = 40 elems = 80B -> conflict-free ldmatrix.
#define BMk 128
#define BNk 128
#define BKk 32
#define ROWB 80                      // bytes per smem row
#define TILEB (128 * ROWB)           // 10240 bytes per operand tile

// epi: 0 = none; 1 = softplus(acc + bias[n]); 2 = also emit hi/lo split for cols < Rsz
__global__ void __launch_bounds__(256)
gemm3_kernel(const bf16* __restrict__ Ah, const bf16* __restrict__ Al,
             const bf16* __restrict__ Bh, const bf16* __restrict__ Bl,
             const float* __restrict__ bias, float* __restrict__ C,
             bf16* __restrict__ Eh, bf16* __restrict__ El,
             int N, int K, int lda, int ldb, int ldc, int epi)
{
    __shared__ __align__(16) char smem[4 * TILEB];   // 40 KB static
    uint32_t sb = smem_to_u32(smem);
    int t = threadIdx.x, wid = t >> 5, lane = t & 31;
    int m0 = blockIdx.y * BMk, n0 = blockIdx.x * BNk;
    int wm = wid >> 2, wn = wid & 3;           // warp tile: rows wm*64, cols wn*32

    float acc[4][4][4];
    #pragma unroll
    for (int i = 0; i < 4; i++)
        #pragma unroll
        for (int j = 0; j < 4; j++)
            #pragma unroll
            for (int v = 0; v < 4; v++) acc[i][j][v] = 0.f;

    // per-lane ldmatrix byte offsets
    uint32_t a_off = (uint32_t)((wm * 64 + (lane & 15)) * ROWB + ((lane >> 4) * 8) * 2);
    uint32_t b_off = (uint32_t)((wn * 32 + ((lane >> 4) & 1) * 8 + (lane & 7)) * ROWB
                                + (((lane >> 3) & 1) * 8) * 2);

    // precompute this thread's 8 load slots (2048 16B-chunks / 256 threads)
    const bf16* srcb[8];
    uint32_t    dsto[8];
    #pragma unroll
    for (int i = 0; i < 8; i++) {
        int cid = t + i * 256;               // 0..2047
        int tile = cid >> 9;                 // 0:Ah 1:Al 2:Bh 3:Bl
        int idx  = cid & 511;
        int row  = idx >> 2;
        int ch   = idx & 3;
        dsto[i] = (uint32_t)(tile * TILEB + row * ROWB + ch * 16);
        if (tile == 0)      srcb[i] = Ah + (size_t)(m0 + row) * lda + ch * 8;
        else if (tile == 1) srcb[i] = Al + (size_t)(m0 + row) * lda + ch * 8;
        else {
            int n  = n0 + row;
            int cr = (n < N) ? n : 0;        // OOB rows: row 0 (affects only unstored cols)
            srcb[i] = ((tile == 2) ? Bh : Bl) + (size_t)cr * ldb + ch * 8;
        }
    }

    const int KT = K / BKk;
    uint4 pf[8];

    // prologue: fetch tile 0 -> regs -> smem
    #pragma unroll
    for (int i = 0; i < 8; i++) pf[i] = *(const uint4*)(srcb[i]);
    #pragma unroll
    for (int i = 0; i < 8; i++) *(uint4*)(smem + dsto[i]) = pf[i];
    __syncthreads();

    for (int it = 0; it < KT; it++) {
        // prefetch next tile into registers (LDG latency hidden by MMA work below)
        if (it + 1 < KT) {
            int k0 = (it + 1) * BKk;
            #pragma unroll
            for (int i = 0; i < 8; i++) pf[i] = *(const uint4*)(srcb[i] + k0);
        }

        #pragma unroll
        for (int ks = 0; ks < 2; ks++) {
            uint32_t bh[8], bl[8];
            uint32_t bbase = sb + 2 * TILEB + b_off + ks * 32;
            ldsm4(bh[0], bh[1], bh[2], bh[3], bbase);
            ldsm4(bh[4], bh[5], bh[6], bh[7], bbase + 16 * ROWB);
            bbase += TILEB;
            ldsm4(bl[0], bl[1], bl[2], bl[3], bbase);
            ldsm4(bl[4], bl[5], bl[6], bl[7], bbase + 16 * ROWB);

            #pragma unroll
            for (int mi = 0; mi < 4; mi++) {
                uint32_t ah0, ah1, ah2, ah3, al0, al1, al2, al3;
                uint32_t abase = sb + a_off + mi * 16 * ROWB + ks * 32;
                ldsm4(ah0, ah1, ah2, ah3, abase);
                ldsm4(al0, al1, al2, al3, abase + TILEB);
                #pragma unroll
                for (int j = 0; j < 4; j++) {
                    mma16816(acc[mi][j], ah0, ah1, ah2, ah3, bh[j*2], bh[j*2+1]);
                    mma16816(acc[mi][j], ah0, ah1, ah2, ah3, bl[j*2], bl[j*2+1]);
                    mma16816(acc[mi][j], al0, al1, al2, al3, bh[j*2], bh[j*2+1]);
                }
            }
        }
        __syncthreads();                       // all reads of smem done
        if (it + 1 < KT) {
            #pragma unroll
            for (int i = 0; i < 8; i++) *(uint4*)(smem + dsto[i]) = pf[i];
            __syncthreads();                   // smem ready for next iteration
        }
    }

    // epilogue: direct register -> gmem stores
    #pragma unroll
    for (int mi = 0; mi < 4; mi++) {
        int row = m0 + wm * 64 + mi * 16 + (lane >> 2);
        #pragma unroll
        for (int j = 0; j < 4; j++) {
            int col = n0 + wn * 32 + j * 8 + (lane & 3) * 2;
            if (col < N) {
                float v0 = acc[mi][j][0], v1 = acc[mi][j][1];
                float v2 = acc[mi][j][2], v3 = acc[mi][j][3];
                if (epi == 1) {
                    float b0 = bias[col], b1 = bias[col + 1];
                    v0 += b0; v1 += b1; v2 += b0; v3 += b1;
                    v0 = (v0 > 0.f) ? v0 + log1pf(__expf(-v0)) : log1pf(__expf(v0));
                    v1 = (v1 > 0.f) ? v1 + log1pf(__expf(-v1)) : log1pf(__expf(v1));
                    v2 = (v2 > 0.f) ? v2 + log1pf(__expf(-v2)) : log1pf(__expf(v2));
                    v3 = (v3 > 0.f) ? v3 + log1pf(__expf(-v3)) : log1pf(__expf(v3));
                }
                *(float2*)(C + (size_t)row * ldc + col)       = make_float2(v0, v1);
                *(float2*)(C + (size_t)(row + 8) * ldc + col) = make_float2(v2, v3);
                if (epi == 2 && col < Rsz) {
                    // hi/lo split of dt_in for the downstream dt GEMM
                    bf16 h0 = __float2bfloat16(v0);
                    bf16 h1 = __float2bfloat16(v1);
                    bf16 h2 = __float2bfloat16(v2);
                    bf16 h3 = __float2bfloat16(v3);
                    size_t r0i = (size_t)row * Rsz + col;
                    size_t r1i = (size_t)(row + 8) * Rsz + col;
                    Eh[r0i]     = h0; El[r0i]     = __float2bfloat16(v0 - __bfloat162float(h0));
                    Eh[r0i + 1] = h1; El[r0i + 1] = __float2bfloat16(v1 - __bfloat162float(h1));
                    Eh[r1i]     = h2; El[r1i]     = __float2bfloat16(v2 - __bfloat162float(h2));
                    Eh[r1i + 1] = h3; El[r1i + 1] = __float2bfloat16(v3 - __bfloat162float(h3));
                }
            }
        }
    }
}

// ---------------- 1) x = h + r ; residual_out = x ; xn_hi/lo = rmsnorm(x) ----------------
__global__ __launch_bounds__(256) void add_rmsnorm_kernel(
    const float* __restrict__ h, const float* __restrict__ r,
    const float* __restrict__ w, float* __restrict__ resid_out,
    bf16* __restrict__ xh, bf16* __restrict__ xl)
{
    int row = blockIdx.x;
    const float4* hp = (const float4*)(h + (size_t)row * Hsz);
    const float4* rp = (const float4*)(r + (size_t)row * Hsz);
    float4*       ro = (float4*)(resid_out + (size_t)row * Hsz);
    const float4* wp = (const float4*)w;
    int t = threadIdx.x;

    float4 v0, v1;
    { float4 a = hp[t], b = rp[t];
      v0 = make_float4(a.x+b.x, a.y+b.y, a.z+b.z, a.w+b.w);
      a = hp[t+256]; b = rp[t+256];
      v1 = make_float4(a.x+b.x, a.y+b.y, a.z+b.z, a.w+b.w); }
    float s = v0.x*v0.x+v0.y*v0.y+v0.z*v0.z+v0.w*v0.w
            + v1.x*v1.x+v1.y*v1.y+v1.z*v1.z+v1.w*v1.w;
    __shared__ float red[8];
    #pragma unroll
    for (int o = 16; o > 0; o >>= 1) s += __shfl_xor_sync(0xffffffffu, s, o);
    if ((t & 31) == 0) red[t >> 5] = s;
    __syncthreads();
    if (t == 0) { float tot = 0.f; for (int i = 0; i < 8; i++) tot += red[i]; red[0] = tot; }
    __syncthreads();
    float inv = rsqrtf(red[0] * (1.0f / Hsz) + 1e-5f);

    ro[t] = v0; ro[t + 256] = v1;
    float4 w0 = wp[t], w1 = wp[t + 256];
    float o0[8] = {v0.x*inv*w0.x, v0.y*inv*w0.y, v0.z*inv*w0.z, v0.w*inv*w0.w,
                   v1.x*inv*w1.x, v1.y*inv*w1.y, v1.z*inv*w1.z, v1.w*inv*w1.w};
    size_t base = (size_t)row * Hsz;
    #pragma unroll
    for (int j = 0; j < 4; j++) {
        bf16 hh = __float2bfloat16(o0[j]);
        xh[base + t*4 + j] = hh;
        xl[base + t*4 + j] = __float2bfloat16(o0[j] - __bfloat162float(hh));
    }
    #pragma unroll
    for (int j = 0; j < 4; j++) {
        bf16 hh = __float2bfloat16(o0[4 + j]);
        xh[base + 1024 + t*4 + j] = hh;
        xl[base + 1024 + t*4 + j] = __float2bfloat16(o0[4 + j] - __bfloat162float(hh));
    }
}

// ---------------- generic f32 -> (hi,lo) bf16 ----------------
__global__ __launch_bounds__(256) void cvt_hilo_kernel(
    const float* __restrict__ s, bf16* __restrict__ hi, bf16* __restrict__ lo, size_t n)
{
    size_t i = (size_t)blockIdx.x * 256 + threadIdx.x;
    size_t stride = (size_t)gridDim.x * 256;
    for (; i < n; i += stride) {
        float v = s[i];
        bf16 h = __float2bfloat16(v);
        hi[i] = h;
        lo[i] = __float2bfloat16(v - __bfloat162float(h));
    }
}

// ---------------- 3) causal depthwise conv (K=4) + silu -> hi/lo ----------------
#define CONV_CHUNK 256
__global__ __launch_bounds__(256) void conv_silu_kernel(
    const float* __restrict__ xz, const float* __restrict__ cw,
    const float* __restrict__ cb, bf16* __restrict__ xh, bf16* __restrict__ xl)
{
    int d  = blockIdx.x * 256 + threadIdx.x;
    int l0 = blockIdx.y * CONV_CHUNK;
    int b  = blockIdx.z;
    size_t base = (size_t)b * Lsz;

    float w0 = cw[d*4+0], w1 = cw[d*4+1], w2 = cw[d*4+2], w3 = cw[d*4+3];
    float bias = cb[d];
    float xm3 = (l0 >= 3) ? xz[(base + l0 - 3) * (2*Dsz) + d] : 0.f;
    float xm2 = (l0 >= 2) ? xz[(base + l0 - 2) * (2*Dsz) + d] : 0.f;
    float xm1 = (l0 >= 1) ? xz[(base + l0 - 1) * (2*Dsz) + d] : 0.f;

    #pragma unroll 4
    for (int l = l0; l < l0 + CONV_CHUNK; l++) {
        float x0 = xz[(base + l) * (2*Dsz) + d];
        float v  = fmaf(w0, xm3, fmaf(w1, xm2, fmaf(w2, xm1, fmaf(w3, x0, bias))));
        float sv = v / (1.f + __expf(-v));
        bf16 hh = __float2bfloat16(sv);
        xh[(base + l) * Dsz + d] = hh;
        xl[(base + l) * Dsz + d] = __float2bfloat16(sv - __bfloat162float(hh));
        xm3 = xm2; xm2 = xm1; xm1 = x0;
    }
}

// ---------------- 5) selective scan: 4 lanes per (b,d), split over N ----------------
__global__ __launch_bounds__(128) void scan4_kernel(
    const float* __restrict__ dt, const bf16* __restrict__ xch, const bf16* __restrict__ xcl,
    const float* __restrict__ dbl, const float* __restrict__ xz,
    const float* __restrict__ A_log, const float* __restrict__ D_param,
    bf16* __restrict__ yh, bf16* __restrict__ yl)
{
    int gid = blockIdx.x * 128 + threadIdx.x;    // 65536 threads
    int sub = gid & 3;
    int pr  = gid >> 2;                          // (b,d)
    int d = pr & (Dsz - 1);
    int b = pr >> 12;

    float A[4], h[4];
    #pragma unroll
    for (int j = 0; j < 4; j++) {
        A[j] = -expf(A_log[d * Nst + sub * 4 + j]);
        h[j] = 0.f;
    }
    float Dp = D_param[d];
    size_t rb = (size_t)b * Lsz;

    for (int l = 0; l < Lsz; l++) {
        size_t row = rb + l;
        float dtv = dt[row * Dsz + d];
        float xv  = __bfloat162float(xch[row * Dsz + d]) + __bfloat162float(xcl[row * Dsz + d]);
        float zv  = xz[row * (2*Dsz) + Dsz + d];
        const float* bc = dbl + row * DBLW;
        float4 Bv = *(const float4*)(bc + Rsz + sub * 4);
        float4 Cv = *(const float4*)(bc + Rsz + Nst + sub * 4);

        float dtx = dtv * xv;
        float ys = 0.f;
        h[0] = fmaf(__expf(dtv * A[0]), h[0], dtx * Bv.x); ys = fmaf(h[0], Cv.x, ys);
        h[1] = fmaf(__expf(dtv * A[1]), h[1], dtx * Bv.y); ys = fmaf(h[1], Cv.y, ys);
        h[2] = fmaf(__expf(dtv * A[2]), h[2], dtx * Bv.z); ys = fmaf(h[2], Cv.z, ys);
        h[3] = fmaf(__expf(dtv * A[3]), h[3], dtx * Bv.w); ys = fmaf(h[3], Cv.w, ys);
        ys += __shfl_xor_sync(0xffffffffu, ys, 1);
        ys += __shfl_xor_sync(0xffffffffu, ys, 2);

        if (sub == 0) {
            float yv = fmaf(xv, Dp, ys);
            float sg = zv / (1.f + __expf(-zv));
            float o  = yv * sg;
            bf16 hh = __float2bfloat16(o);
            yh[row * Dsz + d] = hh;
            yl[row * Dsz + d] = __float2bfloat16(o - __bfloat162float(hh));
        }
    }
}

// ---------------- launcher ----------------
extern "C" void kernel_launch(void* const* d_in, const int* in_sizes, int n_in,
                              void* d_out, int out_size)
{
    const float* hidden    = (const float*)d_in[0];
    const float* residual  = (const float*)d_in[1];
    const float* norm_w    = (const float*)d_in[2];
    const float* in_proj_w = (const float*)d_in[3];
    const float* conv_w    = (const float*)d_in[4];
    const float* conv_b    = (const float*)d_in[5];
    const float* x_proj_w  = (const float*)d_in[6];
    const float* dt_proj_w = (const float*)d_in[7];
    const float* dt_proj_b = (const float*)d_in[8];
    const float* A_log     = (const float*)d_in[9];
    const float* D_param   = (const float*)d_in[10];
    const float* out_proj_w= (const float*)d_in[11];

    float* out       = (float*)d_out;
    float* resid_out = out + (size_t)Msz * Hsz;

    bf16 *xnh,*xnl,*wih,*wil,*xch,*xcl,*xph,*xpl,*dih,*dil,*dwh,*dwl,*yhh,*yll,*owh,*owl;
    float *xz,*dbl,*dtb;
    cudaGetSymbolAddress((void**)&xnh, g_xn_hi);  cudaGetSymbolAddress((void**)&xnl, g_xn_lo);
    cudaGetSymbolAddress((void**)&wih, g_wip_hi); cudaGetSymbolAddress((void**)&wil, g_wip_lo);
    cudaGetSymbolAddress((void**)&xz,  g_xz);
    cudaGetSymbolAddress((void**)&xch, g_xc_hi);  cudaGetSymbolAddress((void**)&xcl, g_xc_lo);
    cudaGetSymbolAddress((void**)&xph, g_xpw_hi); cudaGetSymbolAddress((void**)&xpl, g_xpw_lo);
    cudaGetSymbolAddress((void**)&dbl, g_dbl);
    cudaGetSymbolAddress((void**)&dih, g_dti_hi); cudaGetSymbolAddress((void**)&dil, g_dti_lo);
    cudaGetSymbolAddress((void**)&dwh, g_dtw_hi); cudaGetSymbolAddress((void**)&dwl, g_dtw_lo);
    cudaGetSymbolAddress((void**)&dtb, g_dt);
    cudaGetSymbolAddress((void**)&yhh, g_y_hi);   cudaGetSymbolAddress((void**)&yll, g_y_lo);
    cudaGetSymbolAddress((void**)&owh, g_opw_hi); cudaGetSymbolAddress((void**)&owl, g_opw_lo);

    // 1) rmsnorm (+ residual passthrough) -> xn hi/lo
    add_rmsnorm_kernel<<<Msz, 256>>>(hidden, residual, norm_w, resid_out, xnh, xnl);

    // weight conversions
    cvt_hilo_kernel<<<2048, 256>>>(in_proj_w,  wih, wil, (size_t)(2*Dsz) * Hsz);
    cvt_hilo_kernel<<<1024, 256>>>(x_proj_w,   xph, xpl, (size_t)DBLW * Dsz);
    cvt_hilo_kernel<<<1024, 256>>>(dt_proj_w,  dwh, dwl, (size_t)Dsz * Rsz);
    cvt_hilo_kernel<<<2048, 256>>>(out_proj_w, owh, owl, (size_t)Hsz * Dsz);

    // 2) in_proj: (8192 x 8192, K=2048) -> xz fp32
    {
        dim3 grid(2*Dsz / BNk, Msz / BMk);
        gemm3_kernel<<<grid, 256>>>(xnh, xnl, wih, wil, nullptr, xz, nullptr, nullptr,
                                    2*Dsz, Hsz, Hsz, Hsz, 2*Dsz, 0);
    }

    // 3) conv + silu -> xc hi/lo
    {
        dim3 grid(Dsz/256, Lsz/CONV_CHUNK, Bsz);
        conv_silu_kernel<<<grid, 256>>>(xz, conv_w, conv_b, xch, xcl);
    }

    // 4) x_proj: (8192 x 160, K=4096) -> dbl fp32 (+ fused dt_in hi/lo extraction)
    {
        dim3 grid((DBLW + BNk - 1)/BNk, Msz / BMk);
        gemm3_kernel<<<grid, 256>>>(xch, xcl, xph, xpl, nullptr, dbl, dih, dil,
                                    DBLW, Dsz, Dsz, Dsz, DBLW, 2);
    }

    // 5) dt: (8192 x 4096, K=128), softplus(+bias) -> dt fp32
    {
        dim3 grid(Dsz / BNk, Msz / BMk);
        gemm3_kernel<<<grid, 256>>>(dih, dil, dwh, dwl, dt_proj_b, dtb, nullptr, nullptr,
                                    Dsz, Rsz, Rsz, Rsz, Dsz, 1);
    }

    // 6) selective scan + gating -> y hi/lo
    scan4_kernel<<<(Bsz * Dsz * 4)/128, 128>>>(dtb, xch, xcl, dbl, xz, A_log, D_param, yhh, yll);

    // 7) out_proj: (8192 x 2048, K=4096) -> out fp32
    {
        dim3 grid(Hsz / BNk, Msz / BMk);
        gemm3_kernel<<<grid, 256>>>(yhh, yll, owh, owl, nullptr, out, nullptr, nullptr,
                                    Hsz, Dsz, Dsz, Dsz, Hsz, 0);
    }
    (void)in_sizes; (void)n_in; (void)out_size;
}